// round 7
// baseline (speedup 1.0000x reference)
#include <cuda_runtime.h>
#include <cuda_bf16.h>

// Problem constants
#define BSZ 32
#define TT  200
#define RR  512
#define FF  128
#define BR  4
#define CC  10
#define K2  1024          // 2*R
#define NNZ 256           // nonzeros per branch row
#define NROWS 2048        // R*BR
#define VTH 0.5f

#define NCTA_TOTAL 148    // all co-resident (1 CTA/SM)
#define GEMM_CTAS  128    // each: 16 branch rows (4 neurons) x 32 batches
#define NTH 1024

#define KT_STRIDE 36      // padded row stride (floats): float4-aligned, conflict-free
#define KT_STRIDE_B (KT_STRIDE*4)

#define OUT0 (BSZ*CC*TT)  // offset of spikes block in d_out

// -------- scratch (device globals) --------
__device__ float    g_currents[TT * RR * BSZ];   // [T][R][B]  (batch-minor)
__device__ float    g_spk[2][RR * BSZ];          // ping-pong spikes [R][B]
__device__ unsigned g_pidx[NROWS * NNZ];         // idx * KT_STRIDE_B (bytes)
__device__ float    g_wv [NROWS * NNZ];          // compacted masked weights
__device__ volatile unsigned g_arrive[160];      // per-CTA arrival flags

__device__ __forceinline__ float sigmoidf_(float x) { return 1.f / (1.f + __expf(-x)); }

// -------- init: reset cross-launch state (graph replays reuse globals) ------
__global__ void k_init() {
    int tid = blockIdx.x * blockDim.x + threadIdx.x;
    int n = 2 * RR * BSZ;
    for (int i = tid; i < n; i += gridDim.x * blockDim.x) ((float*)g_spk)[i] = 0.f;
    if (tid < 160) g_arrive[tid] = 0;
}

// -------- kernel A: currents[t][r][b] = dot(input[b][t][r][:], w_in)+b_in ---
__global__ void k_currents(const float* __restrict__ inp,
                           const float* __restrict__ w_in,
                           const float* __restrict__ b_in) {
    __shared__ float sw[FF];
    int tid = threadIdx.x;
    if (tid < FF) sw[tid] = w_in[tid];
    __syncthreads();
    int lane = tid & 31, wid = tid >> 5;
    long long rid = (long long)blockIdx.x * 8 + wid;   // row over (b,t,r)
    if (rid >= (long long)BSZ * TT * RR) return;
    const float4* p = (const float4*)inp + rid * (FF / 4);
    float4 v = p[lane];
    float4 w = ((const float4*)sw)[lane];
    float s = v.x * w.x + v.y * w.y + v.z * w.z + v.w * w.w;
    #pragma unroll
    for (int o = 16; o; o >>= 1) s += __shfl_xor_sync(0xffffffffu, s, o);
    if (lane == 0) {
        int r = (int)(rid % RR);
        long long bt = rid / RR;
        int t = (int)(bt % TT);
        int b = (int)(bt / TT);
        g_currents[((long long)t * RR + r) * BSZ + b] = s + b_in[0];
    }
}

// -------- prep: compact (w_rnn*mask) rows into 256 (pidx, w) pairs ----------
__global__ void k_prep(const float* __restrict__ w_rnn,
                       const float* __restrict__ mask) {
    int row = blockIdx.x * 8 + (threadIdx.x >> 5);
    int lane = threadIdx.x & 31;
    if (row >= NROWS) return;
    int base = 0;
    for (int c0 = 0; c0 < K2; c0 += 32) {
        float m = mask[(long long)row * K2 + c0 + lane];
        unsigned bal = __ballot_sync(0xffffffffu, m != 0.f);
        int pre = __popc(bal & ((1u << lane) - 1u));
        if (m != 0.f) {
            int pos = base + pre;
            if (pos < NNZ) {
                g_pidx[row * NNZ + pos] = (unsigned)(c0 + lane) * KT_STRIDE_B;
                g_wv [row * NNZ + pos] = w_rnn[(long long)row * K2 + c0 + lane];
            }
        }
        base += __popc(bal);
    }
}

// distributed global barrier: every CTA's warp0 polls all arrival flags
__device__ __forceinline__ void step_barrier(int tid, int bid, unsigned target) {
    __syncthreads();
    if (tid == 0) { __threadfence(); g_arrive[bid] = target; }
    if (tid < 32) {
        bool done = false;
        while (!done) {
            bool ok = true;
            #pragma unroll
            for (int k = 0; k < 5; k++) {
                int i = tid + k * 32;
                unsigned v = (i < NCTA_TOTAL) ? g_arrive[i] : target;
                if (v < target) ok = false;
            }
            done = __all_sync(0xffffffffu, ok);
            if (!done) __nanosleep(30);
        }
        if (tid == 0) __threadfence();
    }
    __syncthreads();
}

// -------- kernel B: persistent recurrent scan -------------------------------
__global__ void __launch_bounds__(NTH, 1)
k_recurrent(const float* __restrict__ gating,
            const float* __restrict__ b_rnn,
            const float* __restrict__ tau_m,
            const float* __restrict__ tau_n,
            const float* __restrict__ w_ro,
            const float* __restrict__ b_ro,
            const float* __restrict__ tau_m_ro,
            float* __restrict__ out) {
    extern __shared__ char sm[];

    int tid = threadIdx.x, lane = tid & 31, wid = tid >> 5;
    int bid = blockIdx.x;

    if (bid >= GEMM_CTAS) {
        // ================= readout CTAs (20) =================
        float* s_wro = (float*)sm;                        // 10*512 f32 = 20KB
        float* s_sp  = s_wro + CC * RR;                   // 512*33 f32 ~67.6KB
        for (int i = tid; i < CC * RR; i += NTH) s_wro[i] = w_ro[i];
        __syncthreads();

        int task = (bid - GEMM_CTAS) * 32 + wid;          // 0..639; tasks < 320
        bool act = task < BSZ * CC;
        int b_ = act ? task / CC : 0, c_ = act ? task % CC : 0;
        float ao = sigmoidf_(tau_m_ro[c_]), bro = b_ro[c_];
        float m0 = 0.f, sp0 = 0.f;

        for (int t = 0; t < TT; t++) {
            step_barrier(tid, bid, (unsigned)(t + 1));
            // stage spikes [r][b] -> smem padded [r*33+b]  (conflict-free dot)
            const float* spn = g_spk[(t + 1) & 1];
            for (int e = tid; e < RR * BSZ; e += NTH) {
                int r = e >> 5, b = e & 31;
                s_sp[r * 33 + b] = __ldcg(spn + e);
            }
            __syncthreads();
            if (act) {
                float sum = 0.f;
                #pragma unroll
                for (int i = 0; i < RR; i += 32)
                    sum += s_sp[(i + lane) * 33 + b_] * s_wro[c_ * RR + i + lane];
                #pragma unroll
                for (int o = 16; o; o >>= 1) sum += __shfl_xor_sync(0xffffffffu, sum, o);
                m0 = m0 * ao + (1.f - ao) * (sum + bro) - VTH * sp0;
                sp0 = (m0 - VTH) > 0.f ? 1.f : 0.f;
                if (lane == 0) out[(long long)task * TT + t] = m0;
            }
            __syncthreads();   // protect s_sp before next stage fill
        }
        return;
    }

    // ================= GEMM CTAs (128) =================
    float*    s_w    = (float*)sm;                               // 16*256 f32 (16KB)
    unsigned* s_pidx = (unsigned*)(s_w + 16 * NNZ);              // 16*256 u32 (16KB)
    float*    s_kT   = (float*)(s_pidx + 16 * NNZ);              // 1024*36 f32 (144KB)
    float*    s_part = s_kT + K2 * KT_STRIDE;                    // 32*32 (half-row partials)
    float*    s_d    = s_part + 32 * 32;                         // 128*4
    float*    s_mem  = s_d + 128 * 4;                            // 128
    float*    s_spk  = s_mem + 128;                              // 128
    float*    s_beta = s_spk + 128;                              // 16
    float*    s_brnn = s_beta + 16;                              // 16
    float*    s_alphaN = s_brnn + 16;                            // 4

    int row0 = bid * 16;          // global branch-row base (16 rows = 4 neurons)
    int n0 = bid * 4;             // global neuron base

    for (int i = tid; i < 16 * NNZ; i += NTH) {
        s_w[i]    = g_wv  [row0 * NNZ + i];
        s_pidx[i] = g_pidx[row0 * NNZ + i];
    }
    if (tid < 16) {
        s_beta[tid] = sigmoidf_(tau_n[(n0 + (tid >> 2)) * BR + (tid & 3)]);
        s_brnn[tid] = b_rnn[row0 + tid];
    }
    if (tid < 4) s_alphaN[tid] = sigmoidf_(tau_m[n0 + tid]);
    if (tid < 128) {
        s_mem[tid] = 0.f; s_spk[tid] = 0.f;
        #pragma unroll
        for (int br = 0; br < BR; br++) s_d[tid * 4 + br] = 0.f;
    }
    __syncthreads();

    // prologue: full kT fill for t=0 (spikes are zeroed by k_init)
    {
        const float4* cur = (const float4*)g_currents;
        const float4* sp  = (const float4*)(g_spk[0]);
        #pragma unroll
        for (int i = tid; i < RR * BSZ / 4; i += NTH) {
            int r = i >> 3, b4 = i & 7;          // 8 float4 per row of 32 batches
            *(float4*)(s_kT + r * KT_STRIDE + b4 * 4)        = __ldcg(cur + i);
            *(float4*)(s_kT + (RR + r) * KT_STRIDE + b4 * 4) = __ldcg(sp + i);
        }
    }
    __syncthreads();

    const char* ktb = (const char*)s_kT + lane * 4;   // lane = batch column

    for (int t = 0; t < TT; t++) {
        // prefetch gating for phase 3 (latency hidden behind GEMM)
        float gpre = 0.f;
        if (tid < 128) {
            int b = tid >> 2, nl = tid & 3;
            gpre = __ldg(&gating[((long long)b * TT + t) * RR + (n0 + nl)]);
        }

        // ---- sparse GEMM: 2 warps per row (128 nnz each), lane = batch -----
        {
            int row = wid >> 1;
            int ho = (wid & 1) * 128;
            const float*    wp = s_w    + row * NNZ + ho;
            const unsigned* pp = s_pidx + row * NNZ + ho;
            float a0 = 0.f, a1 = 0.f, a2 = 0.f, a3 = 0.f;
            #pragma unroll 4
            for (int j = 0; j < 128; j += 4) {
                float4 w4 = *(const float4*)(wp + j);
                uint4  q4 = *(const uint4*)(pp + j);
                a0 = fmaf(w4.x, *(const float*)(ktb + q4.x), a0);
                a1 = fmaf(w4.y, *(const float*)(ktb + q4.y), a1);
                a2 = fmaf(w4.z, *(const float*)(ktb + q4.z), a2);
                a3 = fmaf(w4.w, *(const float*)(ktb + q4.w), a3);
            }
            s_part[wid * 32 + lane] = (a0 + a1) + (a2 + a3);
        }
        __syncthreads();

        // ---- phase 3 (warps 0-3)  ||  currents(t+1) fill (warps 4-31) ------
        if (tid < 128) {
            int b = tid >> 2, nl = tid & 3;
            int r = n0 + nl;
            float g = gpre;
            float lin = 0.f;
            #pragma unroll
            for (int br = 0; br < BR; br++) {
                int row = nl * 4 + br;
                float proj = s_part[(2 * row) * 32 + b]
                           + s_part[(2 * row + 1) * 32 + b] + s_brnn[row];
                float beta = s_beta[row];
                float dold = s_d[tid * 4 + br];
                float dnew = beta * dold + (1.f - beta) * proj;
                lin += dnew;
                s_d[tid * 4 + br] = g * dnew + (1.f - g) * dold;
            }
            float alpha = s_alphaN[nl];
            float mold = s_mem[tid];
            float sold = s_spk[tid];
            float mnew = mold * alpha + (1.f - alpha) * lin - VTH * sold;
            float snew = (mnew - VTH) > 0.f ? 1.f : 0.f;
            float mg = g * mnew + (1.f - g) * mold;
            float sg = g * snew + (1.f - g) * sold;
            s_mem[tid] = mg;
            s_spk[tid] = sg;
            g_spk[(t + 1) & 1][r * BSZ + b] = sg;
            out[OUT0 + ((long long)b * RR + r) * TT + t] = sg;
            __threadfence();   // release spike writes before barrier flag
        } else if (t + 1 < TT) {
            const float4* curN = (const float4*)(g_currents + (long long)(t + 1) * RR * BSZ);
            for (int i = tid - 128; i < RR * BSZ / 4; i += NTH - 128) {
                int r = i >> 3, b4 = i & 7;
                *(float4*)(s_kT + r * KT_STRIDE + b4 * 4) = __ldcg(curN + i);
            }
        }

        // ---- global barrier ------------------------------------------------
        step_barrier(tid, bid, (unsigned)(t + 1));

        // ---- spike-half fill for t+1 ---------------------------------------
        if (t + 1 < TT) {
            const float4* spN = (const float4*)(g_spk[(t + 1) & 1]);
            #pragma unroll
            for (int i = tid; i < RR * BSZ / 4; i += NTH) {
                int r = i >> 3, b4 = i & 7;
                *(float4*)(s_kT + (RR + r) * KT_STRIDE + b4 * 4) = __ldcg(spN + i);
            }
            __syncthreads();
        }
    }
}

extern "C" void kernel_launch(void* const* d_in, const int* in_sizes, int n_in,
                              void* d_out, int out_size) {
    const float* inp      = (const float*)d_in[0];
    const float* gating   = (const float*)d_in[1];
    const float* w_in     = (const float*)d_in[2];
    const float* b_in     = (const float*)d_in[3];
    const float* w_rnn    = (const float*)d_in[4];
    const float* b_rnn    = (const float*)d_in[5];
    const float* tau_m    = (const float*)d_in[6];
    const float* tau_n    = (const float*)d_in[7];
    const float* w_ro     = (const float*)d_in[8];
    const float* b_ro     = (const float*)d_in[9];
    const float* tau_m_ro = (const float*)d_in[10];
    const float* mask     = (const float*)d_in[11];
    float* out = (float*)d_out;

    // GEMM CTA smem: 16KB(w)+16KB(pidx)+147456(kT)+4096(part)+2048(d)
    //                +512+512+~150  ~= 187.6 KB
    int smem_bytes = 188416;
    cudaFuncSetAttribute(k_recurrent,
                         cudaFuncAttributeMaxDynamicSharedMemorySize,
                         smem_bytes);

    k_init<<<64, 256>>>();

    long long total_rows = (long long)BSZ * TT * RR;   // 3,276,800
    int gridA = (int)((total_rows + 7) / 8);
    k_currents<<<gridA, 256>>>(inp, w_in, b_in);

    k_prep<<<NROWS / 8, 256>>>(w_rnn, mask);

    k_recurrent<<<NCTA_TOTAL, NTH, smem_bytes>>>(gating, b_rnn, tau_m, tau_n,
                                                 w_ro, b_ro, tau_m_ro, out);
}

// round 8
// speedup vs baseline: 1.4019x; 1.4019x over previous
#include <cuda_runtime.h>
#include <cuda_bf16.h>

#define BSZ 32
#define TT  200
#define RR  512
#define FF  128
#define BR  4
#define CC  10
#define K2  1024
#define NROWS 2048
#define VTH 0.5f

#define NCTA_TOTAL 148
#define GEMM_CTAS  128
#define NTH 1024

#define KT_STRIDE 36
#define KT_STRIDE_B (KT_STRIDE*4)
#define ROWSTRIDE 272          // cur section + spk section, each padded to 8

#define OUT0 (BSZ*CC*TT)

// -------- device scratch --------
__device__ float    g_currents[TT * RR * BSZ];   // [T][R][B]
__device__ float    g_spk[2][RR * BSZ];          // [R][B] ping-pong
__device__ unsigned g_pidx[NROWS * ROWSTRIDE];   // byte offsets (k*KT_STRIDE_B)
__device__ float    g_wv [NROWS * ROWSTRIDE];
__device__ unsigned g_secs[NROWS];               // ncurP | nspkP<<16
__device__ volatile unsigned g_arrive[160];      // 0..127 gemm, 128..147 readout

__device__ __forceinline__ float sigmoidf_(float x) { return 1.f / (1.f + __expf(-x)); }

__global__ void k_init() {
    int tid = blockIdx.x * blockDim.x + threadIdx.x;
    int n = 2 * RR * BSZ;
    for (int i = tid; i < n; i += gridDim.x * blockDim.x) ((float*)g_spk)[i] = 0.f;
    if (tid < 160) g_arrive[tid] = (tid < 148) ? 0u : 0x7FFFFFFFu;
}

__global__ void k_currents(const float* __restrict__ inp,
                           const float* __restrict__ w_in,
                           const float* __restrict__ b_in) {
    __shared__ float sw[FF];
    int tid = threadIdx.x;
    if (tid < FF) sw[tid] = w_in[tid];
    __syncthreads();
    int lane = tid & 31, wid = tid >> 5;
    long long rid = (long long)blockIdx.x * 8 + wid;
    if (rid >= (long long)BSZ * TT * RR) return;
    const float4* p = (const float4*)inp + rid * (FF / 4);
    float4 v = p[lane];
    float4 w = ((const float4*)sw)[lane];
    float s = v.x * w.x + v.y * w.y + v.z * w.z + v.w * w.w;
    #pragma unroll
    for (int o = 16; o; o >>= 1) s += __shfl_xor_sync(0xffffffffu, s, o);
    if (lane == 0) {
        int r = (int)(rid % RR);
        long long bt = rid / RR;
        int t = (int)(bt % TT);
        int b = (int)(bt / TT);
        g_currents[((long long)t * RR + r) * BSZ + b] = s + b_in[0];
    }
}

// compact rows into currents section (k<512) then spikes section (k>=512)
__global__ void k_prep(const float* __restrict__ w_rnn,
                       const float* __restrict__ mask) {
    int row = blockIdx.x * 8 + (threadIdx.x >> 5);
    int lane = threadIdx.x & 31;
    if (row >= NROWS) return;
    unsigned* pp = g_pidx + row * ROWSTRIDE;
    float*    wp = g_wv  + row * ROWSTRIDE;

    int base = 0;
    for (int c0 = 0; c0 < 512; c0 += 32) {
        float m = mask[(long long)row * K2 + c0 + lane];
        unsigned bal = __ballot_sync(0xffffffffu, m != 0.f);
        int pre = __popc(bal & ((1u << lane) - 1u));
        if (m != 0.f) {
            pp[base + pre] = (unsigned)(c0 + lane) * KT_STRIDE_B;
            wp[base + pre] = w_rnn[(long long)row * K2 + c0 + lane];
        }
        base += __popc(bal);
    }
    int ncur = base, ncurP = (ncur + 7) & ~7;
    if (lane < ncurP - ncur) { pp[ncur + lane] = 0; wp[ncur + lane] = 0.f; }

    base = 0;
    for (int c0 = 512; c0 < K2; c0 += 32) {
        float m = mask[(long long)row * K2 + c0 + lane];
        unsigned bal = __ballot_sync(0xffffffffu, m != 0.f);
        int pre = __popc(bal & ((1u << lane) - 1u));
        if (m != 0.f) {
            pp[ncurP + base + pre] = (unsigned)(c0 + lane) * KT_STRIDE_B;
            wp[ncurP + base + pre] = w_rnn[(long long)row * K2 + c0 + lane];
        }
        base += __popc(bal);
    }
    int nspk = base, nspkP = (nspk + 7) & ~7;
    if (lane < nspkP - nspk) { pp[ncurP + nspk + lane] = 0; wp[ncurP + nspk + lane] = 0.f; }
    if (lane == 0) g_secs[row] = (unsigned)ncurP | ((unsigned)nspkP << 16);
}

// smem float offsets (GEMM CTAs)
#define SW_OFF   0
#define SI_OFF   (SW_OFF + 16*ROWSTRIDE)
#define KT_OFF   (SI_OFF + 16*ROWSTRIDE)
#define PA_OFF   (KT_OFF + K2*KT_STRIDE)
#define PB_OFF   (PA_OFF + 32*32)
#define SD_OFF   (PB_OFF + 32*32)
#define SM_OFF   (SD_OFF + 16*33)
#define SS_OFF   (SM_OFF + 4*33)
#define HB_OFF   (SS_OFF + 4*33)
#define BT_OFF   (HB_OFF + 128*9)
#define BN_OFF   (BT_OFF + 16)
#define AL_OFF   (BN_OFF + 16)
#define SEC_OFF  (AL_OFF + 8)
#define SMEM_FLOATS (SEC_OFF + 24)

__device__ __forceinline__ void gemm_section(
    const float* wp, const unsigned* pp, int cnt,
    const char* ktb, float* dst, int lane)
{
    float a0 = 0.f, a1 = 0.f, a2 = 0.f, a3 = 0.f;
    for (int j = 0; j < cnt; j += 8) {
        float4 wA = *(const float4*)(wp + j);
        uint4  qA = *(const uint4*)(pp + j);
        float4 wB = *(const float4*)(wp + j + 4);
        uint4  qB = *(const uint4*)(pp + j + 4);
        a0 = fmaf(wA.x, *(const float*)(ktb + qA.x), a0);
        a1 = fmaf(wA.y, *(const float*)(ktb + qA.y), a1);
        a2 = fmaf(wA.z, *(const float*)(ktb + qA.z), a2);
        a3 = fmaf(wA.w, *(const float*)(ktb + qA.w), a3);
        a0 = fmaf(wB.x, *(const float*)(ktb + qB.x), a0);
        a1 = fmaf(wB.y, *(const float*)(ktb + qB.y), a1);
        a2 = fmaf(wB.z, *(const float*)(ktb + qB.z), a2);
        a3 = fmaf(wB.w, *(const float*)(ktb + qB.w), a3);
    }
    dst[lane] = (a0 + a1) + (a2 + a3);
}

__global__ void __launch_bounds__(NTH, 1)
k_recurrent(const float* __restrict__ gating,
            const float* __restrict__ b_rnn,
            const float* __restrict__ tau_m,
            const float* __restrict__ tau_n,
            const float* __restrict__ w_ro,
            const float* __restrict__ b_ro,
            const float* __restrict__ tau_m_ro,
            float* __restrict__ out) {
    extern __shared__ float smf[];
    int tid = threadIdx.x, lane = tid & 31, wid = tid >> 5;
    int bid = blockIdx.x;

    if (bid >= GEMM_CTAS) {
        // ======== readout CTAs (20) ========
        float* s_wro = smf;
        float* s_sp  = s_wro + CC * RR;
        for (int i = tid; i < CC * RR; i += NTH) s_wro[i] = w_ro[i];
        __syncthreads();

        int task = (bid - GEMM_CTAS) * 32 + wid;
        bool act = task < BSZ * CC;
        int b_ = act ? task / CC : 0, c_ = act ? task % CC : 0;
        float ao = sigmoidf_(tau_m_ro[c_]), bro = b_ro[c_];
        float m0 = 0.f, sp0 = 0.f;
        int myflag = 128 + (bid - GEMM_CTAS);

        for (int t = 0; t < TT; t++) {
            if (tid < 32) {     // wait: all gemm flags >= t+1
                bool need = true;
                while (need) {
                    bool ok = true;
                    #pragma unroll
                    for (int k = 0; k < 4; k++)
                        if (g_arrive[lane + k * 32] < (unsigned)(t + 1)) ok = false;
                    need = !__all_sync(0xffffffffu, ok);
                    if (need) __nanosleep(20);
                }
            }
            __syncthreads();
            const float* spn = g_spk[(t + 1) & 1];
            for (int e = tid; e < RR * BSZ; e += NTH) {
                int r = e >> 5, b = e & 31;
                s_sp[r * 33 + b] = __ldcg(spn + e);
            }
            __syncthreads();
            if (tid == 0) g_arrive[myflag] = (unsigned)(t + 1);  // buffer consumed
            if (act) {
                float sum = 0.f;
                #pragma unroll
                for (int i = 0; i < RR; i += 32)
                    sum += s_sp[(i + lane) * 33 + b_] * s_wro[c_ * RR + i + lane];
                #pragma unroll
                for (int o = 16; o; o >>= 1) sum += __shfl_xor_sync(0xffffffffu, sum, o);
                m0 = m0 * ao + (1.f - ao) * (sum + bro) - VTH * sp0;
                sp0 = (m0 - VTH) > 0.f ? 1.f : 0.f;
                if (lane == 0) out[(long long)task * TT + t] = m0;
            }
            __syncthreads();
        }
        return;
    }

    // ======== GEMM CTAs (128): 16 rows (4 neurons) x 32 batches ========
    float*    s_w    = smf + SW_OFF;
    unsigned* s_pidx = (unsigned*)(smf + SI_OFF);
    float*    s_kT   = smf + KT_OFF;
    float*    s_pA   = smf + PA_OFF;
    float*    s_pB   = smf + PB_OFF;
    float*    s_d    = smf + SD_OFF;
    float*    s_mem  = smf + SM_OFF;
    float*    s_spk  = smf + SS_OFF;
    float*    s_hist = smf + HB_OFF;
    float*    s_beta = smf + BT_OFF;
    float*    s_brnn = smf + BN_OFF;
    float*    s_alph = smf + AL_OFF;
    unsigned* s_secs = (unsigned*)(smf + SEC_OFF);

    int row0 = bid * 16, n0 = bid * 4;

    for (int i = tid; i < 16 * ROWSTRIDE; i += NTH) {
        s_w[i]    = g_wv  [row0 * ROWSTRIDE + i];
        s_pidx[i] = g_pidx[row0 * ROWSTRIDE + i];
    }
    if (tid < 16) {
        s_secs[tid] = g_secs[row0 + tid];
        s_beta[tid] = sigmoidf_(tau_n[(n0 + (tid >> 2)) * BR + (tid & 3)]);
        s_brnn[tid] = b_rnn[row0 + tid];
    }
    if (tid < 4) s_alph[tid] = sigmoidf_(tau_m[n0 + tid]);
    for (int i = tid; i < 16 * 33; i += NTH) s_d[i] = 0.f;
    if (tid < 4 * 33) { s_mem[tid] = 0.f; s_spk[tid] = 0.f; }
    __syncthreads();

    const char* ktb = (const char*)s_kT + lane * 4;

    // prologue: fill currents(0), currents-GEMM(0)
    {
        const float4* cur = (const float4*)g_currents;
        for (int i = tid; i < RR * BSZ / 4; i += NTH) {
            int r = i >> 3, b4 = i & 7;
            *(float4*)(s_kT + r * KT_STRIDE + b4 * 4) = __ldg(cur + i);
        }
    }
    __syncthreads();
    {
        int row = wid >> 1, half = wid & 1;
        int ncurP = s_secs[row] & 0xFFFF;
        int h0 = ((ncurP >> 4) << 3);
        int beg = half ? h0 : 0;
        int cnt = half ? (ncurP - h0) : h0;
        gemm_section(s_w + row * ROWSTRIDE + beg, s_pidx + row * ROWSTRIDE + beg,
                     cnt, ktb, s_pA + (half * 16 + row) * 32, lane);
    }
    __syncthreads();

    for (int t = 0; t < TT; t++) {
        // (A) wait: gemm flags >= t ; readout flags >= max(0, t-1)
        if (tid < 32) {
            unsigned tgG = (unsigned)t;
            unsigned tgR = (t > 0) ? (unsigned)(t - 1) : 0u;
            bool need = (t > 0);
            while (need) {
                bool ok = true;
                #pragma unroll
                for (int k = 0; k < 5; k++) {
                    int i = lane + k * 32;
                    unsigned v = g_arrive[i];
                    if (v < (i < 128 ? tgG : tgR)) ok = false;
                }
                need = !__all_sync(0xffffffffu, ok);
                if (need) __nanosleep(20);
            }
        }
        __syncthreads();

        // (B) fill spike half: spk(t-1)
        {
            const float4* sp = (const float4*)(g_spk[t & 1]);
            for (int i = tid; i < RR * BSZ / 4; i += NTH) {
                int r = i >> 3, b4 = i & 7;
                *(float4*)(s_kT + (RR + r) * KT_STRIDE + b4 * 4) = __ldcg(sp + i);
            }
        }
        float4 gq = make_float4(0.f, 0.f, 0.f, 0.f);
        if (wid == 0)
            gq = __ldg((const float4*)(gating + ((long long)lane * TT + t) * RR + n0));
        __syncthreads();

        // (C) spike GEMM (all 32 warps)
        {
            int row = wid >> 1, half = wid & 1;
            unsigned sec = s_secs[row];
            int ncurP = sec & 0xFFFF, nspkP = sec >> 16;
            int h0 = ((nspkP >> 4) << 3);
            int beg = ncurP + (half ? h0 : 0);
            int cnt = half ? (nspkP - h0) : h0;
            gemm_section(s_w + row * ROWSTRIDE + beg, s_pidx + row * ROWSTRIDE + beg,
                         cnt, ktb, s_pB + (half * 16 + row) * 32, lane);
        }
        __syncthreads();

        // (D) warp0: phase3 + publish  |  warps1-31: fill currents(t+1)
        if (wid == 0) {
            int b = lane;
            float* spout = g_spk[(t + 1) & 1];
            #pragma unroll
            for (int nl = 0; nl < 4; nl++) {
                float g = nl == 0 ? gq.x : nl == 1 ? gq.y : nl == 2 ? gq.z : gq.w;
                float lin = 0.f;
                #pragma unroll
                for (int br = 0; br < BR; br++) {
                    int row = nl * 4 + br;
                    float proj = s_pA[row * 32 + b] + s_pA[(16 + row) * 32 + b]
                               + s_pB[row * 32 + b] + s_pB[(16 + row) * 32 + b]
                               + s_brnn[row];
                    float beta = s_beta[row];
                    float dold = s_d[row * 33 + b];
                    float dnew = beta * dold + (1.f - beta) * proj;
                    lin += dnew;
                    s_d[row * 33 + b] = g * dnew + (1.f - g) * dold;
                }
                float alpha = s_alph[nl];
                float mold = s_mem[nl * 33 + b];
                float sold = s_spk[nl * 33 + b];
                float mnew = mold * alpha + (1.f - alpha) * lin - VTH * sold;
                float snew = (mnew - VTH) > 0.f ? 1.f : 0.f;
                float mg = g * mnew + (1.f - g) * mold;
                float sg = g * snew + (1.f - g) * sold;
                s_mem[nl * 33 + b] = mg;
                s_spk[nl * 33 + b] = sg;
                spout[(n0 + nl) * BSZ + b] = sg;
                s_hist[(nl * 32 + b) * 9 + (t & 7)] = sg;
            }
            __threadfence();
            __syncwarp();
            if (lane == 0) g_arrive[bid] = (unsigned)(t + 1);
        } else if (t + 1 < TT) {
            const float4* curN = (const float4*)(g_currents + (long long)(t + 1) * RR * BSZ);
            for (int i = tid - 32; i < RR * BSZ / 4; i += NTH - 32) {
                int r = i >> 3, b4 = i & 7;
                *(float4*)(s_kT + r * KT_STRIDE + b4 * 4) = __ldg(curN + i);
            }
        }
        __syncthreads();

        // dump spike history every 8 steps (coalesced, off fenced path)
        if ((t & 7) == 7 && tid < 256) {
            int pair = tid >> 1, half = tid & 1;
            int nl = pair >> 5, b = pair & 31;
            const float* h = s_hist + pair * 9 + half * 4;
            float4 v = make_float4(h[0], h[1], h[2], h[3]);
            long long base = OUT0 + ((long long)b * RR + (n0 + nl)) * TT + (t - 7);
            *(float4*)(out + base + half * 4) = v;
        }

        // (E) currents-GEMM(t+1) overlaps other CTAs' skew + barrier
        if (t + 1 < TT) {
            int row = wid >> 1, half = wid & 1;
            int ncurP = s_secs[row] & 0xFFFF;
            int h0 = ((ncurP >> 4) << 3);
            int beg = half ? h0 : 0;
            int cnt = half ? (ncurP - h0) : h0;
            gemm_section(s_w + row * ROWSTRIDE + beg, s_pidx + row * ROWSTRIDE + beg,
                         cnt, ktb, s_pA + (half * 16 + row) * 32, lane);
            __syncthreads();
        }
    }
}

extern "C" void kernel_launch(void* const* d_in, const int* in_sizes, int n_in,
                              void* d_out, int out_size) {
    const float* inp      = (const float*)d_in[0];
    const float* gating   = (const float*)d_in[1];
    const float* w_in     = (const float*)d_in[2];
    const float* b_in     = (const float*)d_in[3];
    const float* w_rnn    = (const float*)d_in[4];
    const float* b_rnn    = (const float*)d_in[5];
    const float* tau_m    = (const float*)d_in[6];
    const float* tau_n    = (const float*)d_in[7];
    const float* w_ro     = (const float*)d_in[8];
    const float* b_ro     = (const float*)d_in[9];
    const float* tau_m_ro = (const float*)d_in[10];
    const float* mask     = (const float*)d_in[11];
    float* out = (float*)d_out;

    int smem_bytes = SMEM_FLOATS * 4 + 256;   // ~198.8 KB
    cudaFuncSetAttribute(k_recurrent,
                         cudaFuncAttributeMaxDynamicSharedMemorySize,
                         smem_bytes);

    k_init<<<64, 256>>>();

    long long total_rows = (long long)BSZ * TT * RR;
    int gridA = (int)((total_rows + 7) / 8);
    k_currents<<<gridA, 256>>>(inp, w_in, b_in);

    k_prep<<<NROWS / 8, 256>>>(w_rnn, mask);

    k_recurrent<<<NCTA_TOTAL, NTH, smem_bytes>>>(gating, b_rnn, tau_m, tau_n,
                                                 w_ro, b_ro, tau_m_ro, out);
}